// round 4
// baseline (speedup 1.0000x reference)
#include <cuda_runtime.h>

#define N_IMG 128
#define N_REG 36
#define N_CAP 128
#define N_WORD 32
#define DIM 1024

// Scratch (device globals — no runtime allocation)
__device__ float g_raw[N_CAP * N_IMG * N_REG * N_WORD];   // raw[c][i][r][w]  ~75.5 MB
__device__ float g_G[N_IMG * N_REG * N_REG];              // image Gram 36x36
__device__ float g_H[N_CAP * N_WORD * N_WORD];            // caption Gram 32x32

typedef unsigned long long u64;

__device__ __forceinline__ u64 ffma2(u64 a, u64 b, u64 c) {
    u64 d;
    asm("fma.rn.f32x2 %0, %1, %2, %3;" : "=l"(d) : "l"(a), "l"(b), "l"(c));
    return d;
}
__device__ __forceinline__ u64 pack_dup(float x) {
    u64 d;
    asm("mov.b64 %0, {%1, %1};" : "=l"(d) : "f"(x));
    return d;
}
__device__ __forceinline__ void unpack2(u64 v, float& lo, float& hi) {
    asm("mov.b64 {%0, %1}, %2;" : "=f"(lo), "=f"(hi) : "l"(v));
}
__device__ __forceinline__ float lrelu(float x) { return fmaxf(x, 0.1f * x); }

// ---------------------------------------------------------------------------
// K1: per-image Gram matrix G_i = images[i] @ images[i]^T  (36x36, K=1024)
// ---------------------------------------------------------------------------
__global__ __launch_bounds__(256) void k_gram_img(const float* __restrict__ imgs) {
    __shared__ float s[N_REG * 132];   // 132 pad: kills same-bank row stride
    int i = blockIdx.x, tid = threadIdx.x;
    float acc[6];
#pragma unroll
    for (int j = 0; j < 6; j++) acc[j] = 0.f;
    const float* base = imgs + (size_t)i * N_REG * DIM;

    for (int k0 = 0; k0 < DIM; k0 += 128) {
        for (int idx = tid; idx < N_REG * 128; idx += 256) {
            int r = idx >> 7, k = idx & 127;
            s[r * 132 + k] = base[r * DIM + k0 + k];
        }
        __syncthreads();
#pragma unroll
        for (int j = 0; j < 6; j++) {
            int e = tid + 256 * j;
            if (e < N_REG * N_REG) {
                int r1 = e / N_REG, r2 = e - r1 * N_REG;
                const float4* pa = (const float4*)(s + r1 * 132);
                const float4* pb = (const float4*)(s + r2 * 132);
                float t = 0.f;
#pragma unroll
                for (int q = 0; q < 32; q++) {
                    float4 a = pa[q], b = pb[q];
                    t += a.x * b.x + a.y * b.y + a.z * b.z + a.w * b.w;
                }
                acc[j] += t;
            }
        }
        __syncthreads();
    }
#pragma unroll
    for (int j = 0; j < 6; j++) {
        int e = tid + 256 * j;
        if (e < N_REG * N_REG) g_G[i * N_REG * N_REG + e] = acc[j];
    }
}

// ---------------------------------------------------------------------------
// K2: per-caption Gram matrix H_c = captions[c] @ captions[c]^T (32x32)
// ---------------------------------------------------------------------------
__global__ __launch_bounds__(256) void k_gram_cap(const float* __restrict__ caps) {
    __shared__ float s[N_WORD * 132];
    int c = blockIdx.x, tid = threadIdx.x;
    float acc[4] = {0.f, 0.f, 0.f, 0.f};
    const float* base = caps + (size_t)c * N_WORD * DIM;

    for (int k0 = 0; k0 < DIM; k0 += 128) {
        for (int idx = tid; idx < N_WORD * 128; idx += 256) {
            int r = idx >> 7, k = idx & 127;
            s[r * 132 + k] = base[r * DIM + k0 + k];
        }
        __syncthreads();
#pragma unroll
        for (int j = 0; j < 4; j++) {
            int e = tid + 256 * j;   // always < 1024
            int r1 = e >> 5, r2 = e & 31;
            const float4* pa = (const float4*)(s + r1 * 132);
            const float4* pb = (const float4*)(s + r2 * 132);
            float t = 0.f;
#pragma unroll
            for (int q = 0; q < 32; q++) {
                float4 a = pa[q], b = pb[q];
                t += a.x * b.x + a.y * b.y + a.z * b.z + a.w * b.w;
            }
            acc[j] += t;
        }
        __syncthreads();
    }
#pragma unroll
    for (int j = 0; j < 4; j++) {
        int e = tid + 256 * j;
        g_H[c * 1024 + e] = acc[j];
    }
}

// ---------------------------------------------------------------------------
// K3: raw[c,i,r,w] = images[i,r,:] . captions[c,w,:]
// One big 4608 x 4096 x 1024 fp32 GEMM (A@B^T), FFMA2 (fma.rn.f32x2) inner.
// Block tile 128x128, BK=16, 256 threads, 8x8 per thread.
// Register-staged prefetch: next K-tile's LDGs issue right after the barrier,
// overlapping L2 latency with the 16-step FFMA2 compute block.
// ---------------------------------------------------------------------------
#define BM 128
#define BN 128
#define BK 16

__global__ __launch_bounds__(256) void k_gemm(const float* __restrict__ A,
                                              const float* __restrict__ B) {
    __shared__ float As[BK][BM];       // 8 KB
    __shared__ float Bs[BK][BN];       // 8 KB
    const int m0 = blockIdx.y * BM;    // image-region rows (4608 total)
    const int n0 = blockIdx.x * BN;    // caption-word cols (4096 total)
    const int tid = threadIdx.x;
    const int tx = tid & 15, ty = tid >> 4;

    // per-thread load slots: q=0,1 -> idx = tid*2+q
    const int row0 = (tid * 2) >> 2;          // same row for q=0,1? no:
    // idx0 = 2*tid, idx1 = 2*tid+1 -> rows (2*tid)>>2 and (2*tid+1)>>2 (equal),
    // kq differs. Precompute both.
    const int idx0 = tid * 2, idx1 = tid * 2 + 1;
    const int r0 = idx0 >> 2, kq0 = (idx0 & 3) * 4;
    const int r1 = idx1 >> 2, kq1 = (idx1 & 3) * 4;
    (void)row0;

    const float* pa0 = A + (size_t)(m0 + r0) * DIM + kq0;
    const float* pa1 = A + (size_t)(m0 + r1) * DIM + kq1;
    const float* pb0 = B + (size_t)(n0 + r0) * DIM + kq0;
    const float* pb1 = B + (size_t)(n0 + r1) * DIM + kq1;

    u64 acc[8][4];
#pragma unroll
    for (int m = 0; m < 8; m++)
#pragma unroll
        for (int p = 0; p < 4; p++) acc[m][p] = 0ull;

    // prologue: load tile 0 into registers
    float4 va0 = *(const float4*)(pa0);
    float4 va1 = *(const float4*)(pa1);
    float4 vb0 = *(const float4*)(pb0);
    float4 vb1 = *(const float4*)(pb1);

    for (int k0 = 0; k0 < DIM; k0 += BK) {
        // stage registers -> smem
        As[kq0 + 0][r0] = va0.x; As[kq0 + 1][r0] = va0.y;
        As[kq0 + 2][r0] = va0.z; As[kq0 + 3][r0] = va0.w;
        As[kq1 + 0][r1] = va1.x; As[kq1 + 1][r1] = va1.y;
        As[kq1 + 2][r1] = va1.z; As[kq1 + 3][r1] = va1.w;
        Bs[kq0 + 0][r0] = vb0.x; Bs[kq0 + 1][r0] = vb0.y;
        Bs[kq0 + 2][r0] = vb0.z; Bs[kq0 + 3][r0] = vb0.w;
        Bs[kq1 + 0][r1] = vb1.x; Bs[kq1 + 1][r1] = vb1.y;
        Bs[kq1 + 2][r1] = vb1.z; Bs[kq1 + 3][r1] = vb1.w;
        __syncthreads();

        // prefetch next tile (LDG latency overlaps compute below)
        if (k0 + BK < DIM) {
            va0 = *(const float4*)(pa0 + k0 + BK);
            va1 = *(const float4*)(pa1 + k0 + BK);
            vb0 = *(const float4*)(pb0 + k0 + BK);
            vb1 = *(const float4*)(pb1 + k0 + BK);
        }

#pragma unroll
        for (int kk = 0; kk < BK; kk++) {
            const float4* ap = (const float4*)(&As[kk][ty * 8]);
            float4 a03 = ap[0], a47 = ap[1];
            u64 a2[8];
            a2[0] = pack_dup(a03.x); a2[1] = pack_dup(a03.y);
            a2[2] = pack_dup(a03.z); a2[3] = pack_dup(a03.w);
            a2[4] = pack_dup(a47.x); a2[5] = pack_dup(a47.y);
            a2[6] = pack_dup(a47.z); a2[7] = pack_dup(a47.w);
            const ulonglong2* bp = (const ulonglong2*)(&Bs[kk][tx * 8]);
            ulonglong2 b01 = bp[0], b23 = bp[1];
            u64 b2[4] = {b01.x, b01.y, b23.x, b23.y};
#pragma unroll
            for (int m = 0; m < 8; m++)
#pragma unroll
                for (int p = 0; p < 4; p++)
                    acc[m][p] = ffma2(a2[m], b2[p], acc[m][p]);
        }
        __syncthreads();
    }

    // scatter into raw[c][i][r][w]
#pragma unroll
    for (int m = 0; m < 8; m++) {
        int gm = m0 + ty * 8 + m;
        int gi = gm / 36, gr = gm - gi * 36;
#pragma unroll
        for (int p = 0; p < 4; p++) {
            float lo, hi;
            unpack2(acc[m][p], lo, hi);
            int gn = n0 + tx * 8 + p * 2;      // even -> lo/hi share caption
            int c = gn >> 5, w = gn & 31;
            int base = ((c * N_IMG + gi) * N_REG + gr) * N_WORD + w;
            g_raw[base] = lo;
            g_raw[base + 1] = hi;
        }
    }
}

// ---------------------------------------------------------------------------
// K4: per-(i,c) pair focal attention + cosine, both directions.
//   t2i: per word w:   b[r] = 20*lrelu(raw[r,w]) / (rownorm_r + eps)
//        softmax over r, focal mask (a*36 - sum > 0), renorm
//        cos = (attn.raw[:,w]) / (|cap_w| * sqrt(attn^T G_i attn))
//   i2t: symmetric with column norms, softmax over w, H_c quadratic form.
// 96 threads: lanes 0-31 -> words, lanes 32-67 -> regions.
// ---------------------------------------------------------------------------
__global__ __launch_bounds__(96) void k_attn(float* __restrict__ out) {
    const int i = blockIdx.x, c = blockIdx.y;
    const int tid = threadIdx.x;

    __shared__ float sraw[N_REG * 33];   // pad 33: conflict-free rows AND cols
    __shared__ float sG[N_REG * N_REG];
    __shared__ float sH[N_WORD * N_WORD];
    __shared__ float rn[N_REG], cn[N_WORD];
    __shared__ float cosT[N_WORD], cosI[N_REG];

    const float* praw = g_raw + (size_t)(c * N_IMG + i) * (N_REG * N_WORD);
    for (int idx = tid; idx < N_REG * N_WORD; idx += 96)
        sraw[(idx >> 5) * 33 + (idx & 31)] = praw[idx];
    const float* pG = g_G + i * (N_REG * N_REG);
    for (int idx = tid; idx < N_REG * N_REG; idx += 96) sG[idx] = pG[idx];
    const float* pH = g_H + c * (N_WORD * N_WORD);
    for (int idx = tid; idx < N_WORD * N_WORD; idx += 96) sH[idx] = pH[idx];
    __syncthreads();

    if (tid < N_REG) {       // row norms over w (t2i l2norm axis)
        float s = 0.f;
#pragma unroll
        for (int w = 0; w < N_WORD; w++) {
            float x = lrelu(sraw[tid * 33 + w]);
            s += x * x;
        }
        rn[tid] = sqrtf(s);
    }
    if (tid < N_WORD) {      // column norms over r (i2t l2norm axis)
        float s = 0.f;
#pragma unroll
        for (int r = 0; r < N_REG; r++) {
            float x = lrelu(sraw[r * 33 + tid]);
            s += x * x;
        }
        cn[tid] = sqrtf(s);
    }
    __syncthreads();

    if (tid < N_WORD) {
        // ---------------- t2i: query = word w = tid ----------------
        const int w = tid;
        float a[N_REG];
        float mx = -1e30f;
#pragma unroll
        for (int r = 0; r < N_REG; r++) {
            float x = 20.f * lrelu(sraw[r * 33 + w]) / (rn[r] + 1e-8f);
            a[r] = x;
            mx = fmaxf(mx, x);
        }
        float s = 0.f;
#pragma unroll
        for (int r = 0; r < N_REG; r++) { float e = __expf(a[r] - mx); a[r] = e; s += e; }
        float inv = 1.f / s;
        float suma = 0.f;
#pragma unroll
        for (int r = 0; r < N_REG; r++) { a[r] *= inv; suma += a[r]; }
        float st = 0.f;
#pragma unroll
        for (int r = 0; r < N_REG; r++) {
            float t = (a[r] * (float)N_REG - suma > 0.f) ? a[r] : 0.f;
            a[r] = t;
            st += t;
        }
        float ist = 1.f / st;
        float num = 0.f;
#pragma unroll
        for (int r = 0; r < N_REG; r++) { a[r] *= ist; num += a[r] * sraw[r * 33 + w]; }
        // quadratic form attn^T G attn   (rows are 144B = 16B aligned)
        float d2 = 0.f;
#pragma unroll
        for (int r = 0; r < N_REG; r++) {
            const float4* g4 = (const float4*)(sG + r * N_REG);
            float t = 0.f;
#pragma unroll
            for (int j = 0; j < 9; j++) {
                float4 v = g4[j];
                t += v.x * a[4 * j] + v.y * a[4 * j + 1] + v.z * a[4 * j + 2] + v.w * a[4 * j + 3];
            }
            d2 += a[r] * t;
        }
        float capn = fmaxf(sqrtf(sH[w * N_WORD + w]), 1e-8f);
        float wn = fmaxf(sqrtf(fmaxf(d2, 0.f)), 1e-8f);
        cosT[w] = num / (capn * wn);
    } else if (tid < 32 + N_REG) {
        // ---------------- i2t: query = region r = tid-32 ----------------
        const int r = tid - 32;
        float a[N_WORD];
        float mx = -1e30f;
#pragma unroll
        for (int w = 0; w < N_WORD; w++) {
            float x = 20.f * lrelu(sraw[r * 33 + w]) / (cn[w] + 1e-8f);
            a[w] = x;
            mx = fmaxf(mx, x);
        }
        float s = 0.f;
#pragma unroll
        for (int w = 0; w < N_WORD; w++) { float e = __expf(a[w] - mx); a[w] = e; s += e; }
        float inv = 1.f / s;
        float suma = 0.f;
#pragma unroll
        for (int w = 0; w < N_WORD; w++) { a[w] *= inv; suma += a[w]; }
        float st = 0.f;
#pragma unroll
        for (int w = 0; w < N_WORD; w++) {
            float t = (a[w] * (float)N_WORD - suma > 0.f) ? a[w] : 0.f;
            a[w] = t;
            st += t;
        }
        float ist = 1.f / st;
        float num = 0.f;
#pragma unroll
        for (int w = 0; w < N_WORD; w++) { a[w] *= ist; num += a[w] * sraw[r * 33 + w]; }
        float d2 = 0.f;
#pragma unroll
        for (int w = 0; w < N_WORD; w++) {
            const float4* h4 = (const float4*)(sH + w * N_WORD);
            float t = 0.f;
#pragma unroll
            for (int j = 0; j < 8; j++) {
                float4 v = h4[j];
                t += v.x * a[4 * j] + v.y * a[4 * j + 1] + v.z * a[4 * j + 2] + v.w * a[4 * j + 3];
            }
            d2 += a[w] * t;
        }
        float imgn = fmaxf(sqrtf(sG[r * N_REG + r]), 1e-8f);
        float wn = fmaxf(sqrtf(fmaxf(d2, 0.f)), 1e-8f);
        cosI[r] = num / (imgn * wn);
    }
    __syncthreads();

    if (tid == 0) {
        float sT = 0.f;
#pragma unroll
        for (int w = 0; w < N_WORD; w++) sT += cosT[w];
        float sI = 0.f;
#pragma unroll
        for (int r = 0; r < N_REG; r++) sI += cosI[r];
        out[i * N_CAP + c] = sT * (1.f / N_WORD) + sI * (1.f / N_REG);
    }
}

// ---------------------------------------------------------------------------
extern "C" void kernel_launch(void* const* d_in, const int* in_sizes, int n_in,
                              void* d_out, int out_size) {
    const float* images = (const float*)d_in[0];     // (128, 36, 1024)
    const float* captions = (const float*)d_in[1];   // (128, 32, 1024)
    float* out = (float*)d_out;                      // (128, 128)

    k_gram_img<<<N_IMG, 256>>>(images);
    k_gram_cap<<<N_CAP, 256>>>(captions);
    k_gemm<<<dim3(4096 / BN, 4608 / BM), 256>>>(images, captions);
    k_attn<<<dim3(N_IMG, N_CAP), 96>>>(out);
}